// round 10
// baseline (speedup 1.0000x reference)
#include <cuda_runtime.h>
#include <cuda_fp16.h>

#define N_NODES 50000
#define N_FEAT  128
#define N_EDGES 600000
#define N_POWERS 3

// fp16 staging copy of x (halves gather traffic + L1 wavefronts).
__device__ __half g_x16[(size_t)N_NODES * N_FEAT];

// 1 if edge_index is genuinely int64 on device, 0 if int32 (JAX x64-off).
__device__ int g_idx_is64;

__global__ void __launch_bounds__(256)
convert_x_kernel(const float* __restrict__ x, const int* __restrict__ ei32)
{
    if (blockIdx.x == 0 && threadIdx.x == 0) {
        int all_zero = 1;
#pragma unroll
        for (int k = 1; k < 256; k += 2) all_zero &= (ei32[k] == 0);
        g_idx_is64 = all_zero;
    }
    const int i = (blockIdx.x * blockDim.x + threadIdx.x) * 4;
    if (i < N_NODES * N_FEAT) {
        const float4 v = *reinterpret_cast<const float4*>(x + i);
        __half2 h0 = __floats2half2_rn(v.x, v.y);
        __half2 h1 = __floats2half2_rn(v.z, v.w);
        uint2 packed;
        packed.x = *reinterpret_cast<unsigned*>(&h0);
        packed.y = *reinterpret_cast<unsigned*>(&h1);
        *reinterpret_cast<uint2*>(&g_x16[i]) = packed;
    }
}

// abs via sign-mask (LOP3 on alu pipe instead of HABS2 on fma pipe).
static __device__ __forceinline__ __half2 habs2_and(__half2 v) {
    unsigned u = *reinterpret_cast<unsigned*>(&v) & 0x7FFF7FFFu;
    return *reinterpret_cast<__half2*>(&u);
}

// Fold half2 -> float (sum of both halves).
static __device__ __forceinline__ float hfold(__half2 a) {
    return __low2float(__hadd2(a, __lowhigh2highlow(a)));
}

static __device__ __forceinline__ void pf_l1(const void* p) {
    asm volatile("prefetch.global.L1 [%0];" :: "l"(p));
}

// 8 lanes per edge, 8 edges per warp-iteration. Group g (0..3) handles the
// adjacent edge pair (2g, 2g+1) = streams (A, B); indices load as int2 /
// longlong2. Lane l owns features [8l,8l+8) (chunk fA) and [64+8l,+8) (fB);
// each warp LDG.128 covers exactly one 128B line per edge-row.
// Two-phase register reuse keeps regs ~64 -> 4 CTAs/SM. Next iteration's
// indices are loaded at iteration top and its 8 gather lines prefetched to
// L1 mid-iteration, so the next LDGs hit L1 instead of ~250-cyc L2.
__global__ void __launch_bounds__(256, 4)
adj_learn_kernel(const void* __restrict__ edge_index_raw,
                 const float* __restrict__ Wa,
                 const float* __restrict__ ba,
                 const float* __restrict__ Wb,
                 const float* __restrict__ bb,
                 float* __restrict__ out)
{
    const int p    = blockIdx.y;
    const int lane = threadIdx.x & 31;
    const int l    = lane & 7;        // lane within edge-group
    const int g    = lane >> 3;       // edge-pair slot 0..3
    const int warp = threadIdx.x >> 5;
    const int warps_per_block = blockDim.x >> 5;
    const int gwarp  = blockIdx.x * warps_per_block + warp;
    const int nwarps = gridDim.x * warps_per_block;

    const int is64 = g_idx_is64;

    const int fA = l * 8;
    const int fB = 64 + l * 8;

    // Per-lane weights: half2 feature-pairs, k=0..3 -> chunk fA, k=4..7 -> fB.
    const float* Wap = Wa + (size_t)p * (N_FEAT * 3);
    __half2 w2[3][8];
#pragma unroll
    for (int k = 0; k < 4; ++k) {
#pragma unroll
        for (int h = 0; h < 3; ++h) {
            w2[h][k]     = __floats2half2_rn(Wap[(fA + 2 * k) * 3 + h],
                                             Wap[(fA + 2 * k + 1) * 3 + h]);
            w2[h][k + 4] = __floats2half2_rn(Wap[(fB + 2 * k) * 3 + h],
                                             Wap[(fB + 2 * k + 1) * 3 + h]);
        }
    }
    const float ba0 = ba[p * 3 + 0];
    const float ba1 = ba[p * 3 + 1];
    const float ba2 = ba[p * 3 + 2];
    const float wb0 = Wb[p * 3 + 0];
    const float wb1 = Wb[p * 3 + 1];
    const float wb2 = Wb[p * 3 + 2];
    const float bbv = bb[p];

    const int*       ei32 = (const int*)edge_index_raw;
    const long long* ei64 = (const long long*)edge_index_raw;
    const size_t src_base = (size_t)p * 2 * N_EDGES;
    const size_t dst_base = src_base + N_EDGES;
    float* outp = out + (size_t)p * N_EDGES;

    const int n_sup = N_EDGES / 8;    // 75000 super-groups of 8 edges

    if (gwarp >= n_sup) return;

    // Indices for the first iteration.
    int sA, sB, dA, dB;
    {
        const int e0 = gwarp * 8 + 2 * g;
        if (is64) {
            const longlong2 s2 = *reinterpret_cast<const longlong2*>(&ei64[src_base + e0]);
            const longlong2 d2 = *reinterpret_cast<const longlong2*>(&ei64[dst_base + e0]);
            sA = (int)s2.x; sB = (int)s2.y; dA = (int)d2.x; dB = (int)d2.y;
        } else {
            const int2 s2 = *reinterpret_cast<const int2*>(&ei32[src_base + e0]);
            const int2 d2 = *reinterpret_cast<const int2*>(&ei32[dst_base + e0]);
            sA = s2.x; sB = s2.y; dA = d2.x; dB = d2.y;
        }
    }

    for (int si = gwarp; si < n_sup; si += nwarps) {
        // Load next iteration's indices first (long latency, used mid-iter
        // for prefetch and next loop trip). Clamp keeps the load in-bounds.
        const int snx = (si + nwarps < n_sup) ? (si + nwarps) : si;
        int sAn, sBn, dAn, dBn;
        {
            const int en = snx * 8 + 2 * g;
            if (is64) {
                const longlong2 s2 = *reinterpret_cast<const longlong2*>(&ei64[src_base + en]);
                const longlong2 d2 = *reinterpret_cast<const longlong2*>(&ei64[dst_base + en]);
                sAn = (int)s2.x; sBn = (int)s2.y; dAn = (int)d2.x; dBn = (int)d2.y;
            } else {
                const int2 s2 = *reinterpret_cast<const int2*>(&ei32[src_base + en]);
                const int2 d2 = *reinterpret_cast<const int2*>(&ei32[dst_base + en]);
                sAn = s2.x; sBn = s2.y; dAn = d2.x; dBn = d2.y;
            }
        }

        const __half* rjA = &g_x16[(size_t)sA * N_FEAT];
        const __half* riA = &g_x16[(size_t)dA * N_FEAT];
        const __half* rjB = &g_x16[(size_t)sB * N_FEAT];
        const __half* riB = &g_x16[(size_t)dB * N_FEAT];

        __half2 a0A = __float2half2_rn(0.f), a1A = a0A, a2A = a0A;
        __half2 a0B = a0A, a1B = a0A, a2B = a0A;

        // ---- Phase 1: fA chunks of all 4 rows (16 data regs) ----
        {
            __half2 jvA[4], ivA[4], jvB[4], ivB[4];
            *reinterpret_cast<uint4*>(jvA) = *reinterpret_cast<const uint4*>(rjA + fA);
            *reinterpret_cast<uint4*>(ivA) = *reinterpret_cast<const uint4*>(riA + fA);
            *reinterpret_cast<uint4*>(jvB) = *reinterpret_cast<const uint4*>(rjB + fA);
            *reinterpret_cast<uint4*>(ivB) = *reinterpret_cast<const uint4*>(riB + fA);
#pragma unroll
            for (int k = 0; k < 4; ++k) {
                const __half2 dhA = habs2_and(__hsub2(jvA[k], ivA[k]));
                const __half2 dhB = habs2_and(__hsub2(jvB[k], ivB[k]));
                a0A = __hfma2(dhA, w2[0][k], a0A);
                a0B = __hfma2(dhB, w2[0][k], a0B);
                a1A = __hfma2(dhA, w2[1][k], a1A);
                a1B = __hfma2(dhB, w2[1][k], a1B);
                a2A = __hfma2(dhA, w2[2][k], a2A);
                a2B = __hfma2(dhB, w2[2][k], a2B);
            }
        }
        // ---- Phase 2: fB chunks (same registers reused) ----
        {
            __half2 jvA[4], ivA[4], jvB[4], ivB[4];
            *reinterpret_cast<uint4*>(jvA) = *reinterpret_cast<const uint4*>(rjA + fB);
            *reinterpret_cast<uint4*>(ivA) = *reinterpret_cast<const uint4*>(riA + fB);
            *reinterpret_cast<uint4*>(jvB) = *reinterpret_cast<const uint4*>(rjB + fB);
            *reinterpret_cast<uint4*>(ivB) = *reinterpret_cast<const uint4*>(riB + fB);

            // Prefetch next iteration's 8 gather lines into L1 while the
            // phase-2 loads are in flight (idx[next] arrived ~300 cyc ago).
            {
                const __half* nrjA = &g_x16[(size_t)sAn * N_FEAT];
                const __half* nriA = &g_x16[(size_t)dAn * N_FEAT];
                const __half* nrjB = &g_x16[(size_t)sBn * N_FEAT];
                const __half* nriB = &g_x16[(size_t)dBn * N_FEAT];
                pf_l1(nrjA + fA); pf_l1(nrjA + fB);
                pf_l1(nriA + fA); pf_l1(nriA + fB);
                pf_l1(nrjB + fA); pf_l1(nrjB + fB);
                pf_l1(nriB + fA); pf_l1(nriB + fB);
            }

#pragma unroll
            for (int k = 0; k < 4; ++k) {
                const __half2 dhA = habs2_and(__hsub2(jvA[k], ivA[k]));
                const __half2 dhB = habs2_and(__hsub2(jvB[k], ivB[k]));
                a0A = __hfma2(dhA, w2[0][k + 4], a0A);
                a0B = __hfma2(dhB, w2[0][k + 4], a0B);
                a1A = __hfma2(dhA, w2[1][k + 4], a1A);
                a1B = __hfma2(dhB, w2[1][k + 4], a1B);
                a2A = __hfma2(dhA, w2[2][k + 4], a2A);
                a2B = __hfma2(dhB, w2[2][k + 4], a2B);
            }
        }

        // Fold halves to fp32.
        const float x0A = hfold(a0A), x1A = hfold(a1A), x2A = hfold(a2A);
        const float x0B = hfold(a0B), x1B = hfold(a1B), x2B = hfold(a2B);

        // Parity-interleaved butterfly: even lanes carry A, odd carry B.
        const bool odd = (lane & 1);
        float t0 = odd ? x0B : x0A;
        float u0 = odd ? x0A : x0B;
        float t1 = odd ? x1B : x1A;
        float u1 = odd ? x1A : x1B;
        float t2 = odd ? x2B : x2A;
        float u2 = odd ? x2A : x2B;
        t0 += __shfl_xor_sync(0xFFFFFFFFu, u0, 1);
        t1 += __shfl_xor_sync(0xFFFFFFFFu, u1, 1);
        t2 += __shfl_xor_sync(0xFFFFFFFFu, u2, 1);
#pragma unroll
        for (int off = 2; off <= 4; off <<= 1) {
            t0 += __shfl_xor_sync(0xFFFFFFFFu, t0, off);
            t1 += __shfl_xor_sync(0xFFFFFFFFu, t1, off);
            t2 += __shfl_xor_sync(0xFFFFFFFFu, t2, off);
        }
        // Even lane of group g holds edge 2g sums; odd lane holds edge 2g+1.

        // Output lane L (0..7) takes edge L: source lane ((L>>1)<<3)|(L&1).
        const int src = ((lane & 6) << 2) | (lane & 1);
        const float y0 = __shfl_sync(0xFFFFFFFFu, t0, src);
        const float y1 = __shfl_sync(0xFFFFFFFFu, t1, src);
        const float y2 = __shfl_sync(0xFFFFFFFFu, t2, src);

        const float h0 = fmaxf(y0 + ba0, 0.f);
        const float h1 = fmaxf(y1 + ba1, 0.f);
        const float h2 = fmaxf(y2 + ba2, 0.f);
        const float z  = h0 * wb0 + h1 * wb1 + h2 * wb2 + bbv;
        const float r  = __fdividef(1.0f, 1.0f + __expf(-z));
        if (lane < 8) outp[si * 8 + lane] = r;

        sA = sAn; sB = sBn; dA = dAn; dB = dBn;
    }
}

extern "C" void kernel_launch(void* const* d_in, const int* in_sizes, int n_in,
                              void* d_out, int out_size)
{
    const float* x  = (const float*)d_in[0];
    const void*  ei = d_in[1];
    const float* Wa = (const float*)d_in[2];
    const float* ba = (const float*)d_in[3];
    const float* Wb = (const float*)d_in[4];
    const float* bb = (const float*)d_in[5];
    float* out = (float*)d_out;

    convert_x_kernel<<<(N_NODES * N_FEAT / 4 + 255) / 256, 256>>>(x, (const int*)ei);

    // 591 CTAs ~= one wave at 4 CTAs/SM x 148 SMs.
    dim3 grid(197, N_POWERS, 1);
    dim3 block(256, 1, 1);
    adj_learn_kernel<<<grid, block>>>(ei, Wa, ba, Wb, bb, out);
}

// round 12
// speedup vs baseline: 1.1443x; 1.1443x over previous
#include <cuda_runtime.h>
#include <cuda_fp16.h>

#define N_NODES 50000
#define N_FEAT  128
#define N_EDGES 600000
#define N_POWERS 3

// fp16 staging copy of x (halves gather traffic + L1 wavefronts).
__device__ __half g_x16[(size_t)N_NODES * N_FEAT];

// 1 if edge_index is genuinely int64 on device, 0 if int32 (JAX x64-off).
__device__ int g_idx_is64;

__global__ void __launch_bounds__(256)
convert_x_kernel(const float* __restrict__ x, const int* __restrict__ ei32)
{
    if (blockIdx.x == 0 && threadIdx.x == 0) {
        int all_zero = 1;
#pragma unroll
        for (int k = 1; k < 256; k += 2) all_zero &= (ei32[k] == 0);
        g_idx_is64 = all_zero;
    }
    const int i = (blockIdx.x * blockDim.x + threadIdx.x) * 4;
    if (i < N_NODES * N_FEAT) {
        const float4 v = *reinterpret_cast<const float4*>(x + i);
        __half2 h0 = __floats2half2_rn(v.x, v.y);
        __half2 h1 = __floats2half2_rn(v.z, v.w);
        uint2 packed;
        packed.x = *reinterpret_cast<unsigned*>(&h0);
        packed.y = *reinterpret_cast<unsigned*>(&h1);
        *reinterpret_cast<uint2*>(&g_x16[i]) = packed;
    }
}

// abs via sign-mask (LOP3 on alu pipe instead of HABS2 on fma pipe).
static __device__ __forceinline__ __half2 habs2_and(__half2 v) {
    unsigned u = *reinterpret_cast<unsigned*>(&v) & 0x7FFF7FFFu;
    return *reinterpret_cast<__half2*>(&u);
}

// Fold half2 -> float (sum of both halves).
static __device__ __forceinline__ float hfold(__half2 a) {
    return __low2float(__hadd2(a, __lowhigh2highlow(a)));
}

// Fold two half2 accumulators into one packed half2 (lane-local sums).
static __device__ __forceinline__ __half2 hfold_pack(__half2 a, __half2 b) {
    const __half2 sa = __hadd2(a, __lowhigh2highlow(a));  // both halves = sum(a)
    const __half2 sb = __hadd2(b, __lowhigh2highlow(b));  // both halves = sum(b)
    return __halves2half2(__low2half(sa), __low2half(sb));
}

static __device__ __forceinline__ __half2 shfl_xor_h2(__half2 v, int off) {
    unsigned u = *reinterpret_cast<unsigned*>(&v);
    u = __shfl_xor_sync(0xFFFFFFFFu, u, off);
    return *reinterpret_cast<__half2*>(&u);
}

// 8 lanes per edge, 8 edges per warp-iteration. Group g (0..3) handles the
// adjacent edge pair (2g, 2g+1) = streams (A, B); indices load as int2 /
// longlong2. Lane l owns features [8l,8l+8) (chunk fA) and [64+8l,+8) (fB);
// each warp LDG.128 covers exactly one 128B line per edge-row.
// Two-phase register reuse keeps regs ~64 -> 4 CTAs/SM.
// Reduction: (h0,h1) packed in one half2 + h2 fp32; parity butterfly over
// the 8-lane group (3 levels, no routing level); lanes 8g/8g+1 store edges
// 2g/2g+1 directly -> one coalesced 32B store per warp.
__global__ void __launch_bounds__(256, 4)
adj_learn_kernel(const void* __restrict__ edge_index_raw,
                 const float* __restrict__ Wa,
                 const float* __restrict__ ba,
                 const float* __restrict__ Wb,
                 const float* __restrict__ bb,
                 float* __restrict__ out)
{
    const int p    = blockIdx.y;
    const int lane = threadIdx.x & 31;
    const int l    = lane & 7;        // lane within edge-group
    const int g    = lane >> 3;       // edge-pair slot 0..3
    const int warp = threadIdx.x >> 5;
    const int warps_per_block = blockDim.x >> 5;
    const int gwarp  = blockIdx.x * warps_per_block + warp;
    const int nwarps = gridDim.x * warps_per_block;

    const int is64 = g_idx_is64;

    const int fA = l * 8;
    const int fB = 64 + l * 8;

    // Per-lane weights: half2 feature-pairs, k=0..3 -> chunk fA, k=4..7 -> fB.
    const float* Wap = Wa + (size_t)p * (N_FEAT * 3);
    __half2 w2[3][8];
#pragma unroll
    for (int k = 0; k < 4; ++k) {
#pragma unroll
        for (int h = 0; h < 3; ++h) {
            w2[h][k]     = __floats2half2_rn(Wap[(fA + 2 * k) * 3 + h],
                                             Wap[(fA + 2 * k + 1) * 3 + h]);
            w2[h][k + 4] = __floats2half2_rn(Wap[(fB + 2 * k) * 3 + h],
                                             Wap[(fB + 2 * k + 1) * 3 + h]);
        }
    }
    const float ba0 = ba[p * 3 + 0];
    const float ba1 = ba[p * 3 + 1];
    const float ba2 = ba[p * 3 + 2];
    const float wb0 = Wb[p * 3 + 0];
    const float wb1 = Wb[p * 3 + 1];
    const float wb2 = Wb[p * 3 + 2];
    const float bbv = bb[p];

    const int*       ei32 = (const int*)edge_index_raw;
    const long long* ei64 = (const long long*)edge_index_raw;
    const size_t src_base = (size_t)p * 2 * N_EDGES;
    const size_t dst_base = src_base + N_EDGES;
    float* outp = out + (size_t)p * N_EDGES;

    const int n_sup = N_EDGES / 8;    // 75000 super-groups of 8 edges

    for (int si = gwarp; si < n_sup; si += nwarps) {
        // Indices for edge pair (2g, 2g+1): one vector load each for src/dst.
        int sA, sB, dA, dB;
        if (is64) {
            const longlong2 s2 = *reinterpret_cast<const longlong2*>(&ei64[src_base + si * 8 + 2 * g]);
            const longlong2 d2 = *reinterpret_cast<const longlong2*>(&ei64[dst_base + si * 8 + 2 * g]);
            sA = (int)s2.x; sB = (int)s2.y;
            dA = (int)d2.x; dB = (int)d2.y;
        } else {
            const int2 s2 = *reinterpret_cast<const int2*>(&ei32[src_base + si * 8 + 2 * g]);
            const int2 d2 = *reinterpret_cast<const int2*>(&ei32[dst_base + si * 8 + 2 * g]);
            sA = s2.x; sB = s2.y;
            dA = d2.x; dB = d2.y;
        }

        const __half* rjA = &g_x16[(size_t)sA * N_FEAT];
        const __half* riA = &g_x16[(size_t)dA * N_FEAT];
        const __half* rjB = &g_x16[(size_t)sB * N_FEAT];
        const __half* riB = &g_x16[(size_t)dB * N_FEAT];

        __half2 a0A = __float2half2_rn(0.f), a1A = a0A, a2A = a0A;
        __half2 a0B = a0A, a1B = a0A, a2B = a0A;

        // ---- Phase 1: fA chunks of all 4 rows (16 data regs) ----
        {
            __half2 jvA[4], ivA[4], jvB[4], ivB[4];
            *reinterpret_cast<uint4*>(jvA) = *reinterpret_cast<const uint4*>(rjA + fA);
            *reinterpret_cast<uint4*>(ivA) = *reinterpret_cast<const uint4*>(riA + fA);
            *reinterpret_cast<uint4*>(jvB) = *reinterpret_cast<const uint4*>(rjB + fA);
            *reinterpret_cast<uint4*>(ivB) = *reinterpret_cast<const uint4*>(riB + fA);
#pragma unroll
            for (int k = 0; k < 4; ++k) {
                const __half2 dhA = habs2_and(__hsub2(jvA[k], ivA[k]));
                const __half2 dhB = habs2_and(__hsub2(jvB[k], ivB[k]));
                a0A = __hfma2(dhA, w2[0][k], a0A);
                a0B = __hfma2(dhB, w2[0][k], a0B);
                a1A = __hfma2(dhA, w2[1][k], a1A);
                a1B = __hfma2(dhB, w2[1][k], a1B);
                a2A = __hfma2(dhA, w2[2][k], a2A);
                a2B = __hfma2(dhB, w2[2][k], a2B);
            }
        }
        // ---- Phase 2: fB chunks (same registers reused) ----
        {
            __half2 jvA[4], ivA[4], jvB[4], ivB[4];
            *reinterpret_cast<uint4*>(jvA) = *reinterpret_cast<const uint4*>(rjA + fB);
            *reinterpret_cast<uint4*>(ivA) = *reinterpret_cast<const uint4*>(riA + fB);
            *reinterpret_cast<uint4*>(jvB) = *reinterpret_cast<const uint4*>(rjB + fB);
            *reinterpret_cast<uint4*>(ivB) = *reinterpret_cast<const uint4*>(riB + fB);
#pragma unroll
            for (int k = 0; k < 4; ++k) {
                const __half2 dhA = habs2_and(__hsub2(jvA[k], ivA[k]));
                const __half2 dhB = habs2_and(__hsub2(jvB[k], ivB[k]));
                a0A = __hfma2(dhA, w2[0][k + 4], a0A);
                a0B = __hfma2(dhB, w2[0][k + 4], a0B);
                a1A = __hfma2(dhA, w2[1][k + 4], a1A);
                a1B = __hfma2(dhB, w2[1][k + 4], a1B);
                a2A = __hfma2(dhA, w2[2][k + 4], a2A);
                a2B = __hfma2(dhB, w2[2][k + 4], a2B);
            }
        }

        // Fold: (h0,h1) packed as half2, h2 as fp32, per stream.
        const __half2 pkA = hfold_pack(a0A, a1A);
        const __half2 pkB = hfold_pack(a0B, a1B);
        const float   x2A = hfold(a2A);
        const float   x2B = hfold(a2B);

        // Parity-interleaved butterfly over the 8-lane group: even lanes
        // carry stream A (edge 2g), odd lanes carry B (edge 2g+1).
        const bool oddl = (lane & 1);
        __half2 pk_keep = oddl ? pkB : pkA;
        __half2 pk_send = oddl ? pkA : pkB;
        float   x2_keep = oddl ? x2B : x2A;
        float   x2_send = oddl ? x2A : x2B;

        __half2 pk = __hadd2(pk_keep, shfl_xor_h2(pk_send, 1));
        float   x2 = x2_keep + __shfl_xor_sync(0xFFFFFFFFu, x2_send, 1);
#pragma unroll
        for (int off = 2; off <= 4; off <<= 1) {
            pk = __hadd2(pk, shfl_xor_h2(pk, off));
            x2 += __shfl_xor_sync(0xFFFFFFFFu, x2, off);
        }
        // Lane 8g now holds edge 2g's (h0,h1,h2); lane 8g+1 holds edge 2g+1's.

        const float y0 = __low2float(pk);
        const float y1 = __high2float(pk);
        const float h0 = fmaxf(y0 + ba0, 0.f);
        const float h1 = fmaxf(y1 + ba1, 0.f);
        const float h2 = fmaxf(x2 + ba2, 0.f);
        const float z  = h0 * wb0 + h1 * wb1 + h2 * wb2 + bbv;
        const float r  = __fdividef(1.0f, 1.0f + __expf(-z));
        // Lanes {8g, 8g+1} store edges {2g, 2g+1}: addresses si*8+0..7,
        // one 32B coalesced wavefront.
        if (l < 2) outp[si * 8 + 2 * g + (lane & 1)] = r;
    }
}

extern "C" void kernel_launch(void* const* d_in, const int* in_sizes, int n_in,
                              void* d_out, int out_size)
{
    const float* x  = (const float*)d_in[0];
    const void*  ei = d_in[1];
    const float* Wa = (const float*)d_in[2];
    const float* ba = (const float*)d_in[3];
    const float* Wb = (const float*)d_in[4];
    const float* bb = (const float*)d_in[5];
    float* out = (float*)d_out;

    convert_x_kernel<<<(N_NODES * N_FEAT / 4 + 255) / 256, 256>>>(x, (const int*)ei);

    // 591 CTAs ~= one wave at 4 CTAs/SM x 148 SMs.
    dim3 grid(197, N_POWERS, 1);
    dim3 block(256, 1, 1);
    adj_learn_kernel<<<grid, block>>>(ei, Wa, ba, Wb, bb, out);
}